// round 2
// baseline (speedup 1.0000x reference)
#include <cuda_runtime.h>
#include <math.h>

#define MAX_N   131072
#define NGRAPH  256
#define MAXSEG  2048
#define POOL_CHUNK 256

// Scratch (static __device__ arrays — no allocation allowed)
__device__ float d_p[MAX_N];        // x[i] . w_rel
__device__ float d_r[MAX_N];        // x[i] . w_root
__device__ float d_s[MAX_N];        // segment-summed p over edges
__device__ float d_score[MAX_N];    // tanh score
__device__ float d_w[MAX_N];        // final per-node weight (score/k if kept, else 0)
__device__ int   d_starts[NGRAPH + 1];

// ---------------------------------------------------------------------------
// K0: per-node dot products p = x.w_rel, r = x.w_root ; zero s.
// One warp per node, float2 vectorized (64 floats = 32 lanes x float2).
// ---------------------------------------------------------------------------
__global__ void k_node_dots(const float* __restrict__ x,
                            const float* __restrict__ w_rel,
                            const float* __restrict__ w_root,
                            int N) {
    int warp = (int)((blockIdx.x * (unsigned)blockDim.x + threadIdx.x) >> 5);
    int lane = threadIdx.x & 31;
    if (warp >= N) return;
    const float2* xv = (const float2*)(x + (size_t)warp * 64);
    float2 v  = xv[lane];
    float2 wr = ((const float2*)w_rel)[lane];
    float2 wt = ((const float2*)w_root)[lane];
    float a = v.x * wr.x + v.y * wr.y;
    float b = v.x * wt.x + v.y * wt.y;
#pragma unroll
    for (int o = 16; o; o >>= 1) {
        a += __shfl_xor_sync(0xffffffffu, a, o);
        b += __shfl_xor_sync(0xffffffffu, b, o);
    }
    if (lane == 0) {
        d_p[warp] = a;
        d_r[warp] = b;
        d_s[warp] = 0.0f;
    }
}

// ---------------------------------------------------------------------------
// K1: edge scatter  s[dst] += p[src]  (scalar per edge). int4 loads.
// ---------------------------------------------------------------------------
__global__ void k_edge_scatter4(const int* __restrict__ ei, int E) {
    int t = blockIdx.x * blockDim.x + threadIdx.x;
    int E4 = E >> 2;
    if (t < E4) {
        int4 s4 = ((const int4*)ei)[t];
        int4 d4 = ((const int4*)(ei + E))[t];
        atomicAdd(&d_s[d4.x], d_p[s4.x]);
        atomicAdd(&d_s[d4.y], d_p[s4.y]);
        atomicAdd(&d_s[d4.z], d_p[s4.z]);
        atomicAdd(&d_s[d4.w], d_p[s4.w]);
    }
}

__global__ void k_edge_scatter1(const int* __restrict__ ei, int E) {
    int t = blockIdx.x * blockDim.x + threadIdx.x;
    if (t < E) {
        atomicAdd(&d_s[ei[E + t]], d_p[ei[t]]);
    }
}

// ---------------------------------------------------------------------------
// K2: score = tanh(s + b_rel + r); detect segment starts; zero out.
// ---------------------------------------------------------------------------
__global__ void k_score_starts(const int* __restrict__ batch,
                               const float* __restrict__ b_rel,
                               float* __restrict__ out,
                               int N) {
    int i = blockIdx.x * blockDim.x + threadIdx.x;
    if (i < NGRAPH * 64) out[i] = 0.0f;
    if (i >= N) return;
    d_score[i] = tanhf(d_s[i] + b_rel[0] + d_r[i]);
    int bi = batch[i];
    if (i == 0) {
        for (int g = 0; g <= bi; ++g) d_starts[g] = 0;
    } else {
        int bp = batch[i - 1];
        for (int g = bp + 1; g <= bi; ++g) d_starts[g] = i;
    }
    if (i == N - 1) {
        for (int g = bi + 1; g <= NGRAPH; ++g) d_starts[g] = N;
    }
}

// ---------------------------------------------------------------------------
// K3a: per-graph exact top-k ranking (lexsort tie-break: score desc, index
// asc). Writes d_w[i] = kept ? score/k : 0. Exactly k nodes kept.
// ---------------------------------------------------------------------------
__global__ void k_rank(void) {
    __shared__ float sc[MAXSEG];

    int g = blockIdx.x;
    int start = d_starts[g];
    int n = d_starts[g + 1] - start;
    int t = threadIdx.x;
    int k = (n + 1) >> 1;               // ceil(0.5 * n)
    float invk = 1.0f / fmaxf((float)k, 1.0f);

    if (n <= MAXSEG) {
        for (int i = t; i < n; i += 256) sc[i] = d_score[start + i];
        __syncthreads();
        for (int i = t; i < n; i += 256) {
            float si = sc[i];
            int cnt = 0;
            for (int j = 0; j < n; ++j) {
                float sj = sc[j];
                cnt += (sj > si) || (sj == si && j < i);
            }
            d_w[start + i] = (cnt < k) ? si * invk : 0.0f;
        }
    } else {
        for (int i = t; i < n; i += 256) {
            float si = d_score[start + i];
            int cnt = 0;
            for (int j = 0; j < n; ++j) {
                float sj = d_score[start + j];
                cnt += (sj > si) || (sj == si && j < i);
            }
            d_w[start + i] = (cnt < k) ? si * invk : 0.0f;
        }
    }
}

// ---------------------------------------------------------------------------
// K3b: node-parallel weighted pooling. Each block streams POOL_CHUNK
// contiguous rows; thread t owns column (t&63), row-group (t>>6). Since
// batch is sorted, register-accumulate per column and flush with a global
// atomicAdd only when graph id changes (~few flushes per thread).
// ---------------------------------------------------------------------------
__global__ void k_pool(const float* __restrict__ x,
                       const int* __restrict__ batch,
                       float* __restrict__ out,
                       int N) {
    int base = blockIdx.x * POOL_CHUNK;
    int end = base + POOL_CHUNK;
    if (end > N) end = N;
    int t = threadIdx.x;
    int col = t & 63;
    int rg = t >> 6;

    float acc = 0.0f;
    int cur = -1;
    for (int row = base + rg; row < end; row += 4) {
        int g = batch[row];
        float w = d_w[row];
        if (g != cur) {
            if (cur >= 0 && acc != 0.0f) atomicAdd(&out[cur * 64 + col], acc);
            acc = 0.0f;
            cur = g;
        }
        if (w != 0.0f) acc += w * x[(size_t)row * 64 + col];
    }
    if (cur >= 0 && acc != 0.0f) atomicAdd(&out[cur * 64 + col], acc);
}

// ---------------------------------------------------------------------------
extern "C" void kernel_launch(void* const* d_in, const int* in_sizes, int n_in,
                              void* d_out, int out_size) {
    const float* x      = (const float*)d_in[0];
    const int*   ei     = (const int*)d_in[1];
    const int*   batch  = (const int*)d_in[2];
    const float* w_rel  = (const float*)d_in[3];
    const float* b_rel  = (const float*)d_in[4];
    const float* w_root = (const float*)d_in[5];
    float*       out    = (float*)d_out;

    int N = in_sizes[2];
    int E = in_sizes[1] / 2;

    {
        long long threads = (long long)N * 32;
        int blocks = (int)((threads + 255) / 256);
        k_node_dots<<<blocks, 256>>>(x, w_rel, w_root, N);
    }
    if ((E & 3) == 0 && E > 0) {
        int E4 = E >> 2;
        k_edge_scatter4<<<(E4 + 255) / 256, 256>>>(ei, E);
    } else if (E > 0) {
        k_edge_scatter1<<<(E + 255) / 256, 256>>>(ei, E);
    }
    k_score_starts<<<(N + 255) / 256, 256>>>(batch, b_rel, out, N);
    k_rank<<<NGRAPH, 256>>>();
    k_pool<<<(N + POOL_CHUNK - 1) / POOL_CHUNK, 256>>>(x, batch, out, N);
}

// round 3
// speedup vs baseline: 1.2052x; 1.2052x over previous
#include <cuda_runtime.h>
#include <math.h>

#define MAX_N    131072
#define NGRAPH   256
#define MAXSEG   1024
#define RSPLIT   4
#define PSPLIT   4
#define PCHUNKMX 512

// Scratch (static __device__ arrays — no allocation allowed)
__device__ float d_p[MAX_N];        // x[i] . w_rel
__device__ float d_r[MAX_N];        // x[i] . w_root
__device__ float d_s[MAX_N];        // segment-summed p over edges
__device__ float d_score[MAX_N];    // tanh score
__device__ float d_w[MAX_N];        // per-node weight (score/k if kept, else 0)
__device__ int   d_starts[NGRAPH + 1];

// ---------------------------------------------------------------------------
// K0: per-node dot products p = x.w_rel, r = x.w_root ; zero s.
// One warp per node, float2 vectorized.
// ---------------------------------------------------------------------------
__global__ void k_node_dots(const float* __restrict__ x,
                            const float* __restrict__ w_rel,
                            const float* __restrict__ w_root,
                            int N) {
    int warp = (int)((blockIdx.x * (unsigned)blockDim.x + threadIdx.x) >> 5);
    int lane = threadIdx.x & 31;
    if (warp >= N) return;
    const float2* xv = (const float2*)(x + (size_t)warp * 64);
    float2 v  = xv[lane];
    float2 wr = ((const float2*)w_rel)[lane];
    float2 wt = ((const float2*)w_root)[lane];
    float a = v.x * wr.x + v.y * wr.y;
    float b = v.x * wt.x + v.y * wt.y;
#pragma unroll
    for (int o = 16; o; o >>= 1) {
        a += __shfl_xor_sync(0xffffffffu, a, o);
        b += __shfl_xor_sync(0xffffffffu, b, o);
    }
    if (lane == 0) {
        d_p[warp] = a;
        d_r[warp] = b;
        d_s[warp] = 0.0f;
    }
}

// ---------------------------------------------------------------------------
// K1: edge scatter  s[dst] += p[src]  (scalar per edge). int4 loads.
// ---------------------------------------------------------------------------
__global__ void k_edge_scatter4(const int* __restrict__ ei, int E) {
    int t = blockIdx.x * blockDim.x + threadIdx.x;
    int E4 = E >> 2;
    if (t < E4) {
        int4 s4 = ((const int4*)ei)[t];
        int4 d4 = ((const int4*)(ei + E))[t];
        atomicAdd(&d_s[d4.x], d_p[s4.x]);
        atomicAdd(&d_s[d4.y], d_p[s4.y]);
        atomicAdd(&d_s[d4.z], d_p[s4.z]);
        atomicAdd(&d_s[d4.w], d_p[s4.w]);
    }
}

__global__ void k_edge_scatter1(const int* __restrict__ ei, int E) {
    int t = blockIdx.x * blockDim.x + threadIdx.x;
    if (t < E) {
        atomicAdd(&d_s[ei[E + t]], d_p[ei[t]]);
    }
}

// ---------------------------------------------------------------------------
// K2: score = tanh(s + b_rel + r); detect segment starts; zero out.
// ---------------------------------------------------------------------------
__global__ void k_score_starts(const int* __restrict__ batch,
                               const float* __restrict__ b_rel,
                               float* __restrict__ out,
                               int N) {
    int i = blockIdx.x * blockDim.x + threadIdx.x;
    if (i < NGRAPH * 64) out[i] = 0.0f;
    if (i >= N) return;
    d_score[i] = tanhf(d_s[i] + b_rel[0] + d_r[i]);
    int bi = batch[i];
    if (i == 0) {
        for (int g = 0; g <= bi; ++g) d_starts[g] = 0;
    } else {
        int bp = batch[i - 1];
        for (int g = bp + 1; g <= bi; ++g) d_starts[g] = i;
    }
    if (i == N - 1) {
        for (int g = bi + 1; g <= NGRAPH; ++g) d_starts[g] = N;
    }
}

// ---------------------------------------------------------------------------
// K3: ranking. #precede(i) = #{j<i: sj>=si} + #{j>i: sj>si}  (exactly the
// lexsort tie-break, no equality compare needed). Each graph split across
// RSPLIT blocks; inner scan vectorized float4 over smem. Writes
// d_w[i] = kept ? score/k : 0.
// ---------------------------------------------------------------------------
__global__ void k_rank(void) {
    __shared__ float sc[MAXSEG + 4];

    int g  = blockIdx.x >> 2;
    int sp = blockIdx.x & 3;
    int start = d_starts[g];
    int n = d_starts[g + 1] - start;
    int t = threadIdx.x;
    int k = (n + 1) >> 1;
    float invk = 1.0f / fmaxf((float)k, 1.0f);

    int chunk = (n + RSPLIT - 1) / RSPLIT;
    int iBase = sp * chunk;
    int iEnd  = iBase + chunk; if (iEnd > n) iEnd = n;

    if (n <= MAXSEG) {
        int nn = (n + 3) & ~3;
        for (int i = t; i < nn; i += 128)
            sc[i] = (i < n) ? d_score[start + i] : -__int_as_float(0x7f800000);
        __syncthreads();
        const float4* v4 = (const float4*)sc;

        for (int i = iBase + t; i < iEnd; i += 128) {
            float si = sc[i];
            int cnt = 0;
            // region 1: j in [0, i), predicate >=
            int i4 = i & ~3;
#pragma unroll 4
            for (int j4 = 0; j4 < i4; j4 += 4) {
                float4 q = v4[j4 >> 2];
                cnt += (q.x >= si) + (q.y >= si) + (q.z >= si) + (q.w >= si);
            }
            for (int j = i4; j < i; ++j) cnt += (sc[j] >= si);
            // region 2: j in (i, nn), predicate >   (pad -inf never counts)
            int j = i + 1;
            int ja = (j + 3) & ~3; if (ja > nn) ja = nn;
            for (; j < ja; ++j) cnt += (sc[j] > si);
#pragma unroll 4
            for (; j < nn; j += 4) {
                float4 q = v4[j >> 2];
                cnt += (q.x > si) + (q.y > si) + (q.z > si) + (q.w > si);
            }
            d_w[start + i] = (cnt < k) ? si * invk : 0.0f;
        }
    } else {
        // fallback: scan scores from global (improbable segment size)
        for (int i = iBase + t; i < iEnd; i += 128) {
            float si = d_score[start + i];
            int cnt = 0;
            for (int j = 0; j < i; ++j)     cnt += (d_score[start + j] >= si);
            for (int j = i + 1; j < n; ++j) cnt += (d_score[start + j] >  si);
            d_w[start + i] = (cnt < k) ? si * invk : 0.0f;
        }
    }
}

// ---------------------------------------------------------------------------
// K4: pooling. Per graph-quarter block: rows known from d_starts (no batch
// reads, no data-dependent branches on global loads). Weights staged in
// smem; smem reduce + 64 atomics per block.
// ---------------------------------------------------------------------------
__global__ void k_pool(const float* __restrict__ x,
                       float* __restrict__ out) {
    __shared__ float sw[PCHUNKMX];
    __shared__ float ps[4][64];

    int g  = blockIdx.x >> 2;
    int sp = blockIdx.x & 3;
    int start = d_starts[g];
    int n = d_starts[g + 1] - start;
    int chunk = (n + PSPLIT - 1) / PSPLIT;
    int r0 = start + sp * chunk;
    int r1 = r0 + chunk; { int lim = start + n; if (r1 > lim) r1 = lim; }
    int t = threadIdx.x;
    int col = t & 63, rg = t >> 6;

    float acc = 0.0f;
    if (chunk <= PCHUNKMX) {
        for (int i = t; i < r1 - r0; i += 256) sw[i] = d_w[r0 + i];
        __syncthreads();
#pragma unroll 4
        for (int row = r0 + rg; row < r1; row += 4) {
            float w = sw[row - r0];                    // warp-uniform
            if (w != 0.0f) acc += w * x[(size_t)row * 64 + col];
        }
    } else {
        for (int row = r0 + rg; row < r1; row += 4) {
            float w = d_w[row];
            if (w != 0.0f) acc += w * x[(size_t)row * 64 + col];
        }
    }
    ps[rg][col] = acc;
    __syncthreads();
    if (t < 64) {
        float v = ps[0][t] + ps[1][t] + ps[2][t] + ps[3][t];
        if (v != 0.0f) atomicAdd(&out[g * 64 + t], v);
    }
}

// ---------------------------------------------------------------------------
extern "C" void kernel_launch(void* const* d_in, const int* in_sizes, int n_in,
                              void* d_out, int out_size) {
    const float* x      = (const float*)d_in[0];
    const int*   ei     = (const int*)d_in[1];
    const int*   batch  = (const int*)d_in[2];
    const float* w_rel  = (const float*)d_in[3];
    const float* b_rel  = (const float*)d_in[4];
    const float* w_root = (const float*)d_in[5];
    float*       out    = (float*)d_out;

    int N = in_sizes[2];
    int E = in_sizes[1] / 2;

    {
        long long threads = (long long)N * 32;
        int blocks = (int)((threads + 255) / 256);
        k_node_dots<<<blocks, 256>>>(x, w_rel, w_root, N);
    }
    if ((E & 3) == 0 && E > 0) {
        int E4 = E >> 2;
        k_edge_scatter4<<<(E4 + 255) / 256, 256>>>(ei, E);
    } else if (E > 0) {
        k_edge_scatter1<<<(E + 255) / 256, 256>>>(ei, E);
    }
    k_score_starts<<<(N + 255) / 256, 256>>>(batch, b_rel, out, N);
    k_rank<<<NGRAPH * RSPLIT, 128>>>();
    k_pool<<<NGRAPH * PSPLIT, 256>>>(x, out);
}

// round 4
// speedup vs baseline: 1.3837x; 1.1481x over previous
#include <cuda_runtime.h>
#include <math.h>

#define MAX_N    131072
#define NGRAPH   256
#define MAXSEG   1024
#define PSPLIT   4
#define PCHUNKMX 512
#define NBINS    4096
#define CHUNKB   16      // bins per thread in the scan (4096/256)

// Scratch (static __device__ arrays — no allocation allowed)
__device__ float d_p[MAX_N];        // x[i] . w_rel
__device__ float d_r[MAX_N];        // x[i] . w_root
__device__ float d_s[MAX_N];        // segment-summed p over edges
__device__ float d_score[MAX_N];    // tanh score
__device__ float d_w[MAX_N];        // per-node weight (score/k if kept, else 0)
__device__ int   d_starts[NGRAPH + 1];

__device__ __forceinline__ unsigned score_key(float s) {
    unsigned u = __float_as_uint(s);
    return (u & 0x80000000u) ? ~u : (u | 0x80000000u);   // monotone: bigger key = bigger score
}
__device__ __forceinline__ float key_score(unsigned k) {
    return (k & 0x80000000u) ? __uint_as_float(k & 0x7fffffffu)
                             : __uint_as_float(~k);
}

// ---------------------------------------------------------------------------
// K0: per-node dot products p = x.w_rel, r = x.w_root ; zero s.
// ---------------------------------------------------------------------------
__global__ void k_node_dots(const float* __restrict__ x,
                            const float* __restrict__ w_rel,
                            const float* __restrict__ w_root,
                            int N) {
    int warp = (int)((blockIdx.x * (unsigned)blockDim.x + threadIdx.x) >> 5);
    int lane = threadIdx.x & 31;
    if (warp >= N) return;
    const float2* xv = (const float2*)(x + (size_t)warp * 64);
    float2 v  = xv[lane];
    float2 wr = ((const float2*)w_rel)[lane];
    float2 wt = ((const float2*)w_root)[lane];
    float a = v.x * wr.x + v.y * wr.y;
    float b = v.x * wt.x + v.y * wt.y;
#pragma unroll
    for (int o = 16; o; o >>= 1) {
        a += __shfl_xor_sync(0xffffffffu, a, o);
        b += __shfl_xor_sync(0xffffffffu, b, o);
    }
    if (lane == 0) {
        d_p[warp] = a;
        d_r[warp] = b;
        d_s[warp] = 0.0f;
    }
}

// ---------------------------------------------------------------------------
// K1: edge scatter  s[dst] += p[src].
// ---------------------------------------------------------------------------
__global__ void k_edge_scatter4(const int* __restrict__ ei, int E) {
    int t = blockIdx.x * blockDim.x + threadIdx.x;
    int E4 = E >> 2;
    if (t < E4) {
        int4 s4 = ((const int4*)ei)[t];
        int4 d4 = ((const int4*)(ei + E))[t];
        atomicAdd(&d_s[d4.x], d_p[s4.x]);
        atomicAdd(&d_s[d4.y], d_p[s4.y]);
        atomicAdd(&d_s[d4.z], d_p[s4.z]);
        atomicAdd(&d_s[d4.w], d_p[s4.w]);
    }
}
__global__ void k_edge_scatter1(const int* __restrict__ ei, int E) {
    int t = blockIdx.x * blockDim.x + threadIdx.x;
    if (t < E) atomicAdd(&d_s[ei[E + t]], d_p[ei[t]]);
}

// ---------------------------------------------------------------------------
// K2: score = tanh(s + b_rel + r); segment starts; zero out.
// ---------------------------------------------------------------------------
__global__ void k_score_starts(const int* __restrict__ batch,
                               const float* __restrict__ b_rel,
                               float* __restrict__ out,
                               int N) {
    int i = blockIdx.x * blockDim.x + threadIdx.x;
    if (i < NGRAPH * 64) out[i] = 0.0f;
    if (i >= N) return;
    d_score[i] = tanhf(d_s[i] + b_rel[0] + d_r[i]);
    int bi = batch[i];
    if (i == 0) {
        for (int g = 0; g <= bi; ++g) d_starts[g] = 0;
    } else {
        int bp = batch[i - 1];
        for (int g = bp + 1; g <= bi; ++g) d_starts[g] = i;
    }
    if (i == N - 1) {
        for (int g = bi + 1; g <= NGRAPH; ++g) d_starts[g] = N;
    }
}

// ---------------------------------------------------------------------------
// K3: O(n) histogram select per graph. Exact lexsort semantics:
// rank(i) = #{j: key_j > key_i} + #{j: key_j == key_i && j < i}; keep rank<k.
// Only the threshold bin needs exact pairwise treatment.
// ---------------------------------------------------------------------------
__global__ void k_rank(void) {
    __shared__ unsigned keys[MAXSEG];
    __shared__ unsigned hist[NBINS];
    __shared__ unsigned chsum[256];
    __shared__ unsigned suf[256];
    __shared__ int s_bin, s_m1, s_ncand;
    __shared__ int cand_idx[MAXSEG];
    __shared__ unsigned cand_key[MAXSEG];

    int g = blockIdx.x;
    int start = d_starts[g];
    int n = d_starts[g + 1] - start;
    int t = threadIdx.x;
    int k = (n + 1) >> 1;
    float invk = 1.0f / fmaxf((float)k, 1.0f);

    if (n > MAXSEG) {
        // improbable fallback: exact O(n^2) from global
        for (int i = t; i < n; i += 256) {
            float si = d_score[start + i];
            int cnt = 0;
            for (int j = 0; j < i; ++j)     cnt += (d_score[start + j] >= si);
            for (int j = i + 1; j < n; ++j) cnt += (d_score[start + j] >  si);
            d_w[start + i] = (cnt < k) ? si * invk : 0.0f;
        }
        return;
    }

    if (t == 0) { s_bin = -1; s_m1 = 0; s_ncand = 0; }
#pragma unroll
    for (int b = 0; b < CHUNKB; ++b) hist[t * CHUNKB + b] = 0;
    __syncthreads();

    for (int i = t; i < n; i += 256) {
        unsigned key = score_key(d_score[start + i]);
        keys[i] = key;
        atomicAdd(&hist[key >> 20], 1u);
    }
    __syncthreads();

    // per-thread chunk sum over its 16 bins
    unsigned cs = 0;
#pragma unroll
    for (int b = 0; b < CHUNKB; ++b) cs += hist[t * CHUNKB + b];
    chsum[t] = cs;
    suf[t] = cs;
    __syncthreads();
    // inclusive suffix sum over 256 chunks (Hillis-Steele)
    for (int off = 1; off < 256; off <<= 1) {
        unsigned add = (t + off < 256) ? suf[t + off] : 0u;
        __syncthreads();
        suf[t] += add;
        __syncthreads();
    }
    // locate threshold chunk, then bin within it (top-down)
    {
        unsigned above = suf[t] - chsum[t];       // count in chunks strictly above
        if ((int)above < k && k <= (int)suf[t]) { // this chunk contains k-th
            int acc = (int)above;
            for (int b = CHUNKB - 1; b >= 0; --b) {
                int h = (int)hist[t * CHUNKB + b];
                if (acc < k && k <= acc + h) { s_bin = t * CHUNKB + b; s_m1 = acc; }
                acc += h;
            }
        }
    }
    __syncthreads();

    int binb = s_bin, m1 = s_m1;
    // classify nodes; collect threshold-bin candidates
    for (int i = t; i < n; i += 256) {
        unsigned key = keys[i];
        int bin = (int)(key >> 20);
        if (bin > binb) {
            d_w[start + i] = key_score(key) * invk;
        } else if (bin < binb) {
            d_w[start + i] = 0.0f;
        } else {
            int c = atomicAdd(&s_ncand, 1);
            cand_idx[c] = i;
            cand_key[c] = key;
        }
    }
    __syncthreads();

    // exact selection among candidates: keep r = k - m1 of them
    int r = k - m1;
    int nc = s_ncand;
    for (int c = t; c < nc; c += 256) {
        unsigned ki = cand_key[c];
        int ii = cand_idx[c];
        int cnt = 0;
        for (int j = 0; j < nc; ++j) {
            unsigned kj = cand_key[j];
            cnt += (kj > ki) || (kj == ki && cand_idx[j] < ii);
        }
        d_w[start + ii] = (cnt < r) ? key_score(ki) * invk : 0.0f;
    }
}

// ---------------------------------------------------------------------------
// K4: pooling. Per graph-quarter block; weights staged in smem.
// ---------------------------------------------------------------------------
__global__ void k_pool(const float* __restrict__ x,
                       float* __restrict__ out) {
    __shared__ float sw[PCHUNKMX];
    __shared__ float ps[4][64];

    int g  = blockIdx.x >> 2;
    int sp = blockIdx.x & 3;
    int start = d_starts[g];
    int n = d_starts[g + 1] - start;
    int chunk = (n + PSPLIT - 1) / PSPLIT;
    int r0 = start + sp * chunk;
    int r1 = r0 + chunk; { int lim = start + n; if (r1 > lim) r1 = lim; }
    int t = threadIdx.x;
    int col = t & 63, rg = t >> 6;

    float acc = 0.0f;
    if (chunk <= PCHUNKMX) {
        for (int i = t; i < r1 - r0; i += 256) sw[i] = d_w[r0 + i];
        __syncthreads();
#pragma unroll 4
        for (int row = r0 + rg; row < r1; row += 4) {
            float w = sw[row - r0];
            if (w != 0.0f) acc += w * x[(size_t)row * 64 + col];
        }
    } else {
        for (int row = r0 + rg; row < r1; row += 4) {
            float w = d_w[row];
            if (w != 0.0f) acc += w * x[(size_t)row * 64 + col];
        }
    }
    ps[rg][col] = acc;
    __syncthreads();
    if (t < 64) {
        float v = ps[0][t] + ps[1][t] + ps[2][t] + ps[3][t];
        if (v != 0.0f) atomicAdd(&out[g * 64 + t], v);
    }
}

// ---------------------------------------------------------------------------
extern "C" void kernel_launch(void* const* d_in, const int* in_sizes, int n_in,
                              void* d_out, int out_size) {
    const float* x      = (const float*)d_in[0];
    const int*   ei     = (const int*)d_in[1];
    const int*   batch  = (const int*)d_in[2];
    const float* w_rel  = (const float*)d_in[3];
    const float* b_rel  = (const float*)d_in[4];
    const float* w_root = (const float*)d_in[5];
    float*       out    = (float*)d_out;

    int N = in_sizes[2];
    int E = in_sizes[1] / 2;

    {
        long long threads = (long long)N * 32;
        int blocks = (int)((threads + 255) / 256);
        k_node_dots<<<blocks, 256>>>(x, w_rel, w_root, N);
    }
    if ((E & 3) == 0 && E > 0) {
        int E4 = E >> 2;
        k_edge_scatter4<<<(E4 + 255) / 256, 256>>>(ei, E);
    } else if (E > 0) {
        k_edge_scatter1<<<(E + 255) / 256, 256>>>(ei, E);
    }
    k_score_starts<<<(N + 255) / 256, 256>>>(batch, b_rel, out, N);
    k_rank<<<NGRAPH, 256>>>();
    k_pool<<<NGRAPH * PSPLIT, 256>>>(x, out);
}

// round 5
// speedup vs baseline: 1.4647x; 1.0585x over previous
#include <cuda_runtime.h>
#include <math.h>

#define MAX_N    131072
#define NGRAPH   256
#define MAXSEG   1024
#define PSPLIT   4
#define PCHUNKMX 512
#define NBINS    4096
#define CHUNKB   16      // bins per thread (4096/256)

// Scratch (static __device__ arrays — no allocation allowed)
__device__ float d_p[MAX_N];        // x[i] . w_rel
__device__ float d_r[MAX_N];        // x[i] . w_root
__device__ float d_s[MAX_N];        // segment-summed p over edges
__device__ float d_score[MAX_N];    // fallback scratch only
__device__ float d_w[MAX_N];        // per-node weight (score/k if kept, else 0)
__device__ int   d_starts[NGRAPH + 1];

__device__ __forceinline__ unsigned score_key(float s) {
    unsigned u = __float_as_uint(s);
    return (u & 0x80000000u) ? ~u : (u | 0x80000000u);   // monotone
}
__device__ __forceinline__ float key_score(unsigned k) {
    return (k & 0x80000000u) ? __uint_as_float(k & 0x7fffffffu)
                             : __uint_as_float(~k);
}
__device__ __forceinline__ int lower_bound_i(const int* a, int n, int v) {
    int lo = 0, hi = n;
    while (lo < hi) {
        int mid = (lo + hi) >> 1;
        if (a[mid] < v) lo = mid + 1; else hi = mid;
    }
    return lo;
}

// ---------------------------------------------------------------------------
// K0: per-node dots p = x.w_rel, r = x.w_root ; zero s ; zero out.
// ---------------------------------------------------------------------------
__global__ void k_node_dots(const float* __restrict__ x,
                            const float* __restrict__ w_rel,
                            const float* __restrict__ w_root,
                            float* __restrict__ out,
                            int N) {
    int gid = blockIdx.x * blockDim.x + threadIdx.x;
    if (gid < NGRAPH * 64) out[gid] = 0.0f;
    int warp = gid >> 5;
    int lane = threadIdx.x & 31;
    if (warp >= N) return;
    const float2* xv = (const float2*)(x + (size_t)warp * 64);
    float2 v  = xv[lane];
    float2 wr = ((const float2*)w_rel)[lane];
    float2 wt = ((const float2*)w_root)[lane];
    float a = v.x * wr.x + v.y * wr.y;
    float b = v.x * wt.x + v.y * wt.y;
#pragma unroll
    for (int o = 16; o; o >>= 1) {
        a += __shfl_xor_sync(0xffffffffu, a, o);
        b += __shfl_xor_sync(0xffffffffu, b, o);
    }
    if (lane == 0) {
        d_p[warp] = a;
        d_r[warp] = b;
        d_s[warp] = 0.0f;
    }
}

// ---------------------------------------------------------------------------
// K1: edge scatter  s[dst] += p[src].
// ---------------------------------------------------------------------------
__global__ void k_edge_scatter4(const int* __restrict__ ei, int E) {
    int t = blockIdx.x * blockDim.x + threadIdx.x;
    int E4 = E >> 2;
    if (t < E4) {
        int4 s4 = ((const int4*)ei)[t];
        int4 d4 = ((const int4*)(ei + E))[t];
        atomicAdd(&d_s[d4.x], d_p[s4.x]);
        atomicAdd(&d_s[d4.y], d_p[s4.y]);
        atomicAdd(&d_s[d4.z], d_p[s4.z]);
        atomicAdd(&d_s[d4.w], d_p[s4.w]);
    }
}
__global__ void k_edge_scatter1(const int* __restrict__ ei, int E) {
    int t = blockIdx.x * blockDim.x + threadIdx.x;
    if (t < E) atomicAdd(&d_s[ei[E + t]], d_p[ei[t]]);
}

// ---------------------------------------------------------------------------
// K2: per-graph fused score+select. Binary-search segment bounds; compute
// score = tanh(s + b + r) on the fly; 4096-bin histogram select with exact
// lexsort tie-break (score desc, index asc). Writes d_w and d_starts.
// ---------------------------------------------------------------------------
__global__ void k_rank(const int* __restrict__ batch,
                       const float* __restrict__ b_rel,
                       int N) {
    __shared__ unsigned keys[MAXSEG];
    __shared__ unsigned hist[NBINS];
    __shared__ unsigned chsum[256];
    __shared__ unsigned suf[256];
    __shared__ int s_se[2];
    __shared__ int s_bin, s_m1, s_ncand;
    __shared__ int cand_idx[MAXSEG];
    __shared__ unsigned cand_key[MAXSEG];

    int g = blockIdx.x;
    int t = threadIdx.x;

    if (t < 2) s_se[t] = lower_bound_i(batch, N, g + t);
    if (t == 0) { s_bin = -1; s_m1 = 0; s_ncand = 0; }
#pragma unroll
    for (int b = 0; b < CHUNKB; ++b) hist[t * CHUNKB + b] = 0;
    __syncthreads();

    int start = s_se[0];
    int end   = s_se[1];
    int n = end - start;
    if (t == 0) d_starts[g] = start;
    if (t == 1 && g == NGRAPH - 1) d_starts[NGRAPH] = end;

    int k = (n + 1) >> 1;
    float invk = 1.0f / fmaxf((float)k, 1.0f);
    float bias = b_rel[0];

    if (n > MAXSEG) {
        // improbable fallback: exact O(n^2) via global scratch
        for (int i = t; i < n; i += 256)
            d_score[start + i] = tanhf(d_s[start + i] + bias + d_r[start + i]);
        __syncthreads();
        for (int i = t; i < n; i += 256) {
            float si = d_score[start + i];
            int cnt = 0;
            for (int j = 0; j < i; ++j)     cnt += (d_score[start + j] >= si);
            for (int j = i + 1; j < n; ++j) cnt += (d_score[start + j] >  si);
            d_w[start + i] = (cnt < k) ? si * invk : 0.0f;
        }
        return;
    }

    for (int i = t; i < n; i += 256) {
        float sc = tanhf(d_s[start + i] + bias + d_r[start + i]);
        unsigned key = score_key(sc);
        keys[i] = key;
        atomicAdd(&hist[key >> 20], 1u);
    }
    __syncthreads();

    // chunk sums
    unsigned cs = 0;
#pragma unroll
    for (int b = 0; b < CHUNKB; ++b) cs += hist[t * CHUNKB + b];
    chsum[t] = cs;
    __syncthreads();

    // single-warp suffix scan over 256 chunk sums (8 per lane)
    if (t < 32) {
        unsigned v[8];
        unsigned tot = 0;
#pragma unroll
        for (int j = 7; j >= 0; --j) {
            tot += chsum[t * 8 + j];
            v[j] = tot;                  // local inclusive suffix
        }
        // inclusive suffix across lanes
        unsigned run = tot;
#pragma unroll
        for (int off = 1; off < 32; off <<= 1) {
            unsigned q = __shfl_down_sync(0xffffffffu, run, off);
            if (t + off < 32) run += q;
        }
        unsigned tail = run - tot;       // exclusive suffix (lanes above)
#pragma unroll
        for (int j = 0; j < 8; ++j) suf[t * 8 + j] = v[j] + tail;
    }
    __syncthreads();

    // threshold chunk -> bin
    {
        unsigned above = suf[t] - chsum[t];
        if ((int)above < k && k <= (int)suf[t]) {
            int acc = (int)above;
            for (int b = CHUNKB - 1; b >= 0; --b) {
                int h = (int)hist[t * CHUNKB + b];
                if (acc < k && k <= acc + h) { s_bin = t * CHUNKB + b; s_m1 = acc; }
                acc += h;
            }
        }
    }
    __syncthreads();

    int binb = s_bin, m1 = s_m1;
    for (int i = t; i < n; i += 256) {
        unsigned key = keys[i];
        int bin = (int)(key >> 20);
        if (bin > binb) {
            d_w[start + i] = key_score(key) * invk;
        } else if (bin < binb) {
            d_w[start + i] = 0.0f;
        } else {
            int c = atomicAdd(&s_ncand, 1);
            cand_idx[c] = i;
            cand_key[c] = key;
        }
    }
    __syncthreads();

    int r = k - m1;
    int nc = s_ncand;
    for (int c = t; c < nc; c += 256) {
        unsigned ki = cand_key[c];
        int ii = cand_idx[c];
        int cnt = 0;
        for (int j = 0; j < nc; ++j) {
            unsigned kj = cand_key[j];
            cnt += (kj > ki) || (kj == ki && cand_idx[j] < ii);
        }
        d_w[start + ii] = (cnt < r) ? key_score(ki) * invk : 0.0f;
    }
}

// ---------------------------------------------------------------------------
// K3: pooling, float4. Block = graph-quarter; 16 row-groups x 16 col-quads.
// ---------------------------------------------------------------------------
__global__ void k_pool(const float* __restrict__ x,
                       float* __restrict__ out) {
    __shared__ float sw[PCHUNKMX];
    __shared__ float ps[16][64];

    int g  = blockIdx.x >> 2;
    int sp = blockIdx.x & 3;
    int start = d_starts[g];
    int n = d_starts[g + 1] - start;
    int chunk = (n + PSPLIT - 1) / PSPLIT;
    int r0 = start + sp * chunk;
    int r1 = r0 + chunk; { int lim = start + n; if (r1 > lim) r1 = lim; }
    int t = threadIdx.x;
    int q  = t & 15;        // col quad
    int rg = t >> 4;        // row group (16)

    const float4* xv = (const float4*)x;
    float4 acc = make_float4(0.f, 0.f, 0.f, 0.f);

    if (chunk <= PCHUNKMX) {
        for (int i = t; i < r1 - r0; i += 256) sw[i] = d_w[r0 + i];
        __syncthreads();
#pragma unroll 4
        for (int row = r0 + rg; row < r1; row += 16) {
            float w = sw[row - r0];
            if (w != 0.0f) {
                float4 v = xv[(size_t)row * 16 + q];
                acc.x += w * v.x; acc.y += w * v.y;
                acc.z += w * v.z; acc.w += w * v.w;
            }
        }
    } else {
        for (int row = r0 + rg; row < r1; row += 16) {
            float w = d_w[row];
            if (w != 0.0f) {
                float4 v = xv[(size_t)row * 16 + q];
                acc.x += w * v.x; acc.y += w * v.y;
                acc.z += w * v.z; acc.w += w * v.w;
            }
        }
    }
    ps[rg][q * 4 + 0] = acc.x;
    ps[rg][q * 4 + 1] = acc.y;
    ps[rg][q * 4 + 2] = acc.z;
    ps[rg][q * 4 + 3] = acc.w;
    __syncthreads();
    if (t < 64) {
        float v = 0.0f;
#pragma unroll
        for (int j = 0; j < 16; ++j) v += ps[j][t];
        if (v != 0.0f) atomicAdd(&out[g * 64 + t], v);
    }
}

// ---------------------------------------------------------------------------
extern "C" void kernel_launch(void* const* d_in, const int* in_sizes, int n_in,
                              void* d_out, int out_size) {
    const float* x      = (const float*)d_in[0];
    const int*   ei     = (const int*)d_in[1];
    const int*   batch  = (const int*)d_in[2];
    const float* w_rel  = (const float*)d_in[3];
    const float* b_rel  = (const float*)d_in[4];
    const float* w_root = (const float*)d_in[5];
    float*       out    = (float*)d_out;

    int N = in_sizes[2];
    int E = in_sizes[1] / 2;

    {
        long long threads = (long long)N * 32;
        int blocks = (int)((threads + 255) / 256);
        k_node_dots<<<blocks, 256>>>(x, w_rel, w_root, out, N);
    }
    if ((E & 3) == 0 && E > 0) {
        int E4 = E >> 2;
        k_edge_scatter4<<<(E4 + 255) / 256, 256>>>(ei, E);
    } else if (E > 0) {
        k_edge_scatter1<<<(E + 255) / 256, 256>>>(ei, E);
    }
    k_rank<<<NGRAPH, 256>>>(batch, b_rel, N);
    k_pool<<<NGRAPH * PSPLIT, 256>>>(x, out);
}

// round 6
// speedup vs baseline: 1.5450x; 1.0548x over previous
#include <cuda_runtime.h>
#include <math.h>

#define MAX_N    131072
#define NGRAPH   256
#define MAXSEG   1024
#define PSPLIT   8
#define PCHUNKMX 512
#define NBINS    4096
#define CHUNKB   16      // bins per thread (4096/256)

// Scratch (static __device__ arrays — no allocation allowed)
__device__ float d_p[MAX_N];        // x[i] . w_rel
__device__ float d_r[MAX_N];        // x[i] . w_root
__device__ float d_s[MAX_N];        // segment-summed p over edges
__device__ float d_score[MAX_N];    // fallback scratch only
__device__ float d_w[MAX_N];        // per-node weight (score/k if kept, else 0)
__device__ int   d_starts[NGRAPH + 1];

__device__ __forceinline__ unsigned score_key(float s) {
    unsigned u = __float_as_uint(s);
    return (u & 0x80000000u) ? ~u : (u | 0x80000000u);   // monotone
}
__device__ __forceinline__ float key_score(unsigned k) {
    return (k & 0x80000000u) ? __uint_as_float(k & 0x7fffffffu)
                             : __uint_as_float(~k);
}
__device__ __forceinline__ int lower_bound_i(const int* a, int n, int v) {
    int lo = 0, hi = n;
    while (lo < hi) {
        int mid = (lo + hi) >> 1;
        if (a[mid] < v) lo = mid + 1; else hi = mid;
    }
    return lo;
}
__device__ __forceinline__ float dot4(float4 a, float4 b) {
    return a.x * b.x + a.y * b.y + a.z * b.z + a.w * b.w;
}

// ---------------------------------------------------------------------------
// K0: per-node dots p = x.w_rel, r = x.w_root ; zero s ; zero out.
// 8 threads/node, 2x float4 per thread.
// ---------------------------------------------------------------------------
__global__ void k_node_dots(const float* __restrict__ x,
                            const float* __restrict__ w_rel,
                            const float* __restrict__ w_root,
                            float* __restrict__ out,
                            int N) {
    int gid = blockIdx.x * blockDim.x + threadIdx.x;
    if (gid < NGRAPH * 64) out[gid] = 0.0f;
    int node = gid >> 3;
    if (node >= N) return;
    int sub = gid & 7;
    const float4* xr = (const float4*)(x + (size_t)node * 64);
    float4 v0 = xr[sub];
    float4 v1 = xr[sub + 8];
    const float4* wrv = (const float4*)w_rel;
    const float4* wtv = (const float4*)w_root;
    float a = dot4(v0, wrv[sub]) + dot4(v1, wrv[sub + 8]);
    float b = dot4(v0, wtv[sub]) + dot4(v1, wtv[sub + 8]);
#pragma unroll
    for (int o = 4; o; o >>= 1) {
        a += __shfl_xor_sync(0xffffffffu, a, o);
        b += __shfl_xor_sync(0xffffffffu, b, o);
    }
    if (sub == 0) {
        d_p[node] = a;
        d_r[node] = b;
        d_s[node] = 0.0f;
    }
}

// ---------------------------------------------------------------------------
// K1: edge scatter  s[dst] += p[src].  8 edges/thread for MLP.
// ---------------------------------------------------------------------------
__global__ void k_edge_scatter8(const int* __restrict__ ei, int E) {
    int t = blockIdx.x * blockDim.x + threadIdx.x;
    int E8 = E >> 3;
    if (t >= E8) return;
    const int4* sv = (const int4*)ei;
    const int4* dv = (const int4*)(ei + E);
    int4 sa = sv[2 * t], sb = sv[2 * t + 1];
    int4 da = dv[2 * t], db = dv[2 * t + 1];
    float p0 = d_p[sa.x], p1 = d_p[sa.y], p2 = d_p[sa.z], p3 = d_p[sa.w];
    float p4 = d_p[sb.x], p5 = d_p[sb.y], p6 = d_p[sb.z], p7 = d_p[sb.w];
    atomicAdd(&d_s[da.x], p0);
    atomicAdd(&d_s[da.y], p1);
    atomicAdd(&d_s[da.z], p2);
    atomicAdd(&d_s[da.w], p3);
    atomicAdd(&d_s[db.x], p4);
    atomicAdd(&d_s[db.y], p5);
    atomicAdd(&d_s[db.z], p6);
    atomicAdd(&d_s[db.w], p7);
}
__global__ void k_edge_scatter_tail(const int* __restrict__ ei, int base, int E) {
    int t = base + blockIdx.x * blockDim.x + threadIdx.x;
    if (t < E) atomicAdd(&d_s[ei[E + t]], d_p[ei[t]]);
}

// ---------------------------------------------------------------------------
// K2: per-graph fused score+select (histogram top-k, exact lexsort ties).
// ---------------------------------------------------------------------------
__global__ void k_rank(const int* __restrict__ batch,
                       const float* __restrict__ b_rel,
                       int N) {
    __shared__ unsigned keys[MAXSEG];
    __shared__ unsigned hist[NBINS];
    __shared__ unsigned chsum[256];
    __shared__ unsigned suf[256];
    __shared__ int s_se[2];
    __shared__ int s_bin, s_m1, s_ncand;
    __shared__ int cand_idx[MAXSEG];
    __shared__ unsigned cand_key[MAXSEG];

    int g = blockIdx.x;
    int t = threadIdx.x;

    if (t < 2) s_se[t] = lower_bound_i(batch, N, g + t);
    if (t == 0) { s_bin = -1; s_m1 = 0; s_ncand = 0; }
#pragma unroll
    for (int b = 0; b < CHUNKB; ++b) hist[t * CHUNKB + b] = 0;
    __syncthreads();

    int start = s_se[0];
    int end   = s_se[1];
    int n = end - start;
    if (t == 0) d_starts[g] = start;
    if (t == 1 && g == NGRAPH - 1) d_starts[NGRAPH] = end;

    int k = (n + 1) >> 1;
    float invk = 1.0f / fmaxf((float)k, 1.0f);
    float bias = b_rel[0];

    if (n > MAXSEG) {
        for (int i = t; i < n; i += 256)
            d_score[start + i] = tanhf(d_s[start + i] + bias + d_r[start + i]);
        __syncthreads();
        for (int i = t; i < n; i += 256) {
            float si = d_score[start + i];
            int cnt = 0;
            for (int j = 0; j < i; ++j)     cnt += (d_score[start + j] >= si);
            for (int j = i + 1; j < n; ++j) cnt += (d_score[start + j] >  si);
            d_w[start + i] = (cnt < k) ? si * invk : 0.0f;
        }
        return;
    }

    for (int i = t; i < n; i += 256) {
        float sc = tanhf(d_s[start + i] + bias + d_r[start + i]);
        unsigned key = score_key(sc);
        keys[i] = key;
        atomicAdd(&hist[key >> 20], 1u);
    }
    __syncthreads();

    unsigned cs = 0;
#pragma unroll
    for (int b = 0; b < CHUNKB; ++b) cs += hist[t * CHUNKB + b];
    chsum[t] = cs;
    __syncthreads();

    if (t < 32) {
        unsigned v[8];
        unsigned tot = 0;
#pragma unroll
        for (int j = 7; j >= 0; --j) {
            tot += chsum[t * 8 + j];
            v[j] = tot;
        }
        unsigned run = tot;
#pragma unroll
        for (int off = 1; off < 32; off <<= 1) {
            unsigned q = __shfl_down_sync(0xffffffffu, run, off);
            if (t + off < 32) run += q;
        }
        unsigned tail = run - tot;
#pragma unroll
        for (int j = 0; j < 8; ++j) suf[t * 8 + j] = v[j] + tail;
    }
    __syncthreads();

    {
        unsigned above = suf[t] - chsum[t];
        if ((int)above < k && k <= (int)suf[t]) {
            int acc = (int)above;
            for (int b = CHUNKB - 1; b >= 0; --b) {
                int h = (int)hist[t * CHUNKB + b];
                if (acc < k && k <= acc + h) { s_bin = t * CHUNKB + b; s_m1 = acc; }
                acc += h;
            }
        }
    }
    __syncthreads();

    int binb = s_bin, m1 = s_m1;
    for (int i = t; i < n; i += 256) {
        unsigned key = keys[i];
        int bin = (int)(key >> 20);
        if (bin > binb) {
            d_w[start + i] = key_score(key) * invk;
        } else if (bin < binb) {
            d_w[start + i] = 0.0f;
        } else {
            int c = atomicAdd(&s_ncand, 1);
            cand_idx[c] = i;
            cand_key[c] = key;
        }
    }
    __syncthreads();

    int r = k - m1;
    int nc = s_ncand;
    for (int c = t; c < nc; c += 256) {
        unsigned ki = cand_key[c];
        int ii = cand_idx[c];
        int cnt = 0;
        for (int j = 0; j < nc; ++j) {
            unsigned kj = cand_key[j];
            cnt += (kj > ki) || (kj == ki && cand_idx[j] < ii);
        }
        d_w[start + ii] = (cnt < r) ? key_score(ki) * invk : 0.0f;
    }
}

// ---------------------------------------------------------------------------
// K3: pooling, float4. Block = graph 1/8th; 16 row-groups x 16 col-quads.
// ---------------------------------------------------------------------------
__global__ void k_pool(const float* __restrict__ x,
                       float* __restrict__ out) {
    __shared__ float sw[PCHUNKMX];
    __shared__ float ps[16][64];

    int g  = blockIdx.x >> 3;
    int sp = blockIdx.x & 7;
    int start = d_starts[g];
    int n = d_starts[g + 1] - start;
    int chunk = (n + PSPLIT - 1) / PSPLIT;
    int r0 = start + sp * chunk;
    int r1 = r0 + chunk; { int lim = start + n; if (r1 > lim) r1 = lim; }
    int t = threadIdx.x;
    int q  = t & 15;        // col quad
    int rg = t >> 4;        // row group (16)

    const float4* xv = (const float4*)x;
    float4 acc = make_float4(0.f, 0.f, 0.f, 0.f);

    if (chunk <= PCHUNKMX) {
        for (int i = t; i < r1 - r0; i += 256) sw[i] = d_w[r0 + i];
        __syncthreads();
#pragma unroll 4
        for (int row = r0 + rg; row < r1; row += 16) {
            float w = sw[row - r0];
            if (w != 0.0f) {
                float4 v = xv[(size_t)row * 16 + q];
                acc.x += w * v.x; acc.y += w * v.y;
                acc.z += w * v.z; acc.w += w * v.w;
            }
        }
    } else {
        for (int row = r0 + rg; row < r1; row += 16) {
            float w = d_w[row];
            if (w != 0.0f) {
                float4 v = xv[(size_t)row * 16 + q];
                acc.x += w * v.x; acc.y += w * v.y;
                acc.z += w * v.z; acc.w += w * v.w;
            }
        }
    }
    ps[rg][q * 4 + 0] = acc.x;
    ps[rg][q * 4 + 1] = acc.y;
    ps[rg][q * 4 + 2] = acc.z;
    ps[rg][q * 4 + 3] = acc.w;
    __syncthreads();
    if (t < 64) {
        float v = 0.0f;
#pragma unroll
        for (int j = 0; j < 16; ++j) v += ps[j][t];
        if (v != 0.0f) atomicAdd(&out[g * 64 + t], v);
    }
}

// ---------------------------------------------------------------------------
extern "C" void kernel_launch(void* const* d_in, const int* in_sizes, int n_in,
                              void* d_out, int out_size) {
    const float* x      = (const float*)d_in[0];
    const int*   ei     = (const int*)d_in[1];
    const int*   batch  = (const int*)d_in[2];
    const float* w_rel  = (const float*)d_in[3];
    const float* b_rel  = (const float*)d_in[4];
    const float* w_root = (const float*)d_in[5];
    float*       out    = (float*)d_out;

    int N = in_sizes[2];
    int E = in_sizes[1] / 2;

    {
        long long threads = (long long)N * 8;
        int blocks = (int)((threads + 255) / 256);
        k_node_dots<<<blocks, 256>>>(x, w_rel, w_root, out, N);
    }
    {
        int E8 = E >> 3;
        if (E8 > 0)
            k_edge_scatter8<<<(E8 + 255) / 256, 256>>>(ei, E);
        int rem = E - (E8 << 3);
        if (rem > 0)
            k_edge_scatter_tail<<<(rem + 255) / 256, 256>>>(ei, E8 << 3, E);
    }
    k_rank<<<NGRAPH, 256>>>(batch, b_rel, N);
    k_pool<<<NGRAPH * PSPLIT, 256>>>(x, out);
}

// round 7
// speedup vs baseline: 1.5557x; 1.0069x over previous
#include <cuda_runtime.h>
#include <math.h>

#define MAX_N    131072
#define NGRAPH   256
#define MAXSEG   1024
#define PSPLIT   4
#define PCHUNKMX 512
#define NBINS    2048
#define CHUNKB   8       // bins per thread (2048/256)

// Scratch (static __device__ arrays — no allocation allowed)
__device__ float d_p[MAX_N];        // x[i] . w_rel
__device__ float d_r[MAX_N];        // x[i] . w_root
__device__ float d_s[MAX_N];        // segment-summed p over edges
__device__ float d_score[MAX_N];    // fallback scratch only
__device__ float d_w[MAX_N];        // per-node weight (score/k if kept, else 0)
__device__ int   d_starts[NGRAPH + 1];

__device__ __forceinline__ unsigned score_key(float s) {
    unsigned u = __float_as_uint(s);
    return (u & 0x80000000u) ? ~u : (u | 0x80000000u);   // monotone
}
__device__ __forceinline__ float key_score(unsigned k) {
    return (k & 0x80000000u) ? __uint_as_float(k & 0x7fffffffu)
                             : __uint_as_float(~k);
}
__device__ __forceinline__ int lower_bound_i(const int* a, int n, int v) {
    int lo = 0, hi = n;
    while (lo < hi) {
        int mid = (lo + hi) >> 1;
        if (a[mid] < v) lo = mid + 1; else hi = mid;
    }
    return lo;
}
__device__ __forceinline__ float dot4(float4 a, float4 b) {
    return a.x * b.x + a.y * b.y + a.z * b.z + a.w * b.w;
}

// ---------------------------------------------------------------------------
// K0: per-node dots p = x.w_rel, r = x.w_root ; zero s ; zero out.
// 8 threads/node, 2x float4 per thread.
// ---------------------------------------------------------------------------
__global__ void k_node_dots(const float* __restrict__ x,
                            const float* __restrict__ w_rel,
                            const float* __restrict__ w_root,
                            float* __restrict__ out,
                            int N) {
    int gid = blockIdx.x * blockDim.x + threadIdx.x;
    if (gid < NGRAPH * 64) out[gid] = 0.0f;
    int node = gid >> 3;
    if (node >= N) return;
    int sub = gid & 7;
    const float4* xr = (const float4*)(x + (size_t)node * 64);
    float4 v0 = xr[sub];
    float4 v1 = xr[sub + 8];
    const float4* wrv = (const float4*)w_rel;
    const float4* wtv = (const float4*)w_root;
    float a = dot4(v0, wrv[sub]) + dot4(v1, wrv[sub + 8]);
    float b = dot4(v0, wtv[sub]) + dot4(v1, wtv[sub + 8]);
#pragma unroll
    for (int o = 4; o; o >>= 1) {
        a += __shfl_xor_sync(0xffffffffu, a, o);
        b += __shfl_xor_sync(0xffffffffu, b, o);
    }
    if (sub == 0) {
        d_p[node] = a;
        d_r[node] = b;
        d_s[node] = 0.0f;
    }
}

// ---------------------------------------------------------------------------
// K1: edge scatter  s[dst] += p[src].  8 edges/thread for MLP.
// ---------------------------------------------------------------------------
__global__ void k_edge_scatter8(const int* __restrict__ ei, int E) {
    int t = blockIdx.x * blockDim.x + threadIdx.x;
    int E8 = E >> 3;
    if (t >= E8) return;
    const int4* sv = (const int4*)ei;
    const int4* dv = (const int4*)(ei + E);
    int4 sa = sv[2 * t], sb = sv[2 * t + 1];
    int4 da = dv[2 * t], db = dv[2 * t + 1];
    float p0 = d_p[sa.x], p1 = d_p[sa.y], p2 = d_p[sa.z], p3 = d_p[sa.w];
    float p4 = d_p[sb.x], p5 = d_p[sb.y], p6 = d_p[sb.z], p7 = d_p[sb.w];
    atomicAdd(&d_s[da.x], p0);
    atomicAdd(&d_s[da.y], p1);
    atomicAdd(&d_s[da.z], p2);
    atomicAdd(&d_s[da.w], p3);
    atomicAdd(&d_s[db.x], p4);
    atomicAdd(&d_s[db.y], p5);
    atomicAdd(&d_s[db.z], p6);
    atomicAdd(&d_s[db.w], p7);
}
__global__ void k_edge_scatter_tail(const int* __restrict__ ei, int base, int E) {
    int t = base + blockIdx.x * blockDim.x + threadIdx.x;
    if (t < E) atomicAdd(&d_s[ei[E + t]], d_p[ei[t]]);
}

// ---------------------------------------------------------------------------
// K2: per-graph fused score+select (histogram top-k, exact lexsort ties).
// ---------------------------------------------------------------------------
__global__ void k_rank(const int* __restrict__ batch,
                       const float* __restrict__ b_rel,
                       int N) {
    __shared__ unsigned keys[MAXSEG];
    __shared__ unsigned hist[NBINS];
    __shared__ unsigned chsum[256];
    __shared__ unsigned suf[256];
    __shared__ int s_se[2];
    __shared__ int s_bin, s_m1, s_ncand;
    __shared__ int cand_idx[MAXSEG];
    __shared__ unsigned cand_key[MAXSEG];

    int g = blockIdx.x;
    int t = threadIdx.x;

    if (t < 2) s_se[t] = lower_bound_i(batch, N, g + t);
    if (t == 0) { s_bin = -1; s_m1 = 0; s_ncand = 0; }
#pragma unroll
    for (int b = 0; b < CHUNKB; ++b) hist[t * CHUNKB + b] = 0;
    __syncthreads();

    int start = s_se[0];
    int end   = s_se[1];
    int n = end - start;
    if (t == 0) d_starts[g] = start;
    if (t == 1 && g == NGRAPH - 1) d_starts[NGRAPH] = end;

    int k = (n + 1) >> 1;
    float invk = 1.0f / fmaxf((float)k, 1.0f);
    float bias = b_rel[0];

    if (n > MAXSEG) {
        for (int i = t; i < n; i += 256)
            d_score[start + i] = tanhf(d_s[start + i] + bias + d_r[start + i]);
        __syncthreads();
        for (int i = t; i < n; i += 256) {
            float si = d_score[start + i];
            int cnt = 0;
            for (int j = 0; j < i; ++j)     cnt += (d_score[start + j] >= si);
            for (int j = i + 1; j < n; ++j) cnt += (d_score[start + j] >  si);
            d_w[start + i] = (cnt < k) ? si * invk : 0.0f;
        }
        return;
    }

    for (int i = t; i < n; i += 256) {
        float sc = tanhf(d_s[start + i] + bias + d_r[start + i]);
        unsigned key = score_key(sc);
        keys[i] = key;
        atomicAdd(&hist[key >> 21], 1u);
    }
    __syncthreads();

    unsigned cs = 0;
#pragma unroll
    for (int b = 0; b < CHUNKB; ++b) cs += hist[t * CHUNKB + b];
    chsum[t] = cs;
    __syncthreads();

    // single-warp suffix scan over 256 chunk sums (8 per lane)
    if (t < 32) {
        unsigned v[8];
        unsigned tot = 0;
#pragma unroll
        for (int j = 7; j >= 0; --j) {
            tot += chsum[t * 8 + j];
            v[j] = tot;
        }
        unsigned run = tot;
#pragma unroll
        for (int off = 1; off < 32; off <<= 1) {
            unsigned q = __shfl_down_sync(0xffffffffu, run, off);
            if (t + off < 32) run += q;
        }
        unsigned tail = run - tot;
#pragma unroll
        for (int j = 0; j < 8; ++j) suf[t * 8 + j] = v[j] + tail;
    }
    __syncthreads();

    {
        unsigned above = suf[t] - chsum[t];
        if ((int)above < k && k <= (int)suf[t]) {
            int acc = (int)above;
            for (int b = CHUNKB - 1; b >= 0; --b) {
                int h = (int)hist[t * CHUNKB + b];
                if (acc < k && k <= acc + h) { s_bin = t * CHUNKB + b; s_m1 = acc; }
                acc += h;
            }
        }
    }
    __syncthreads();

    int binb = s_bin, m1 = s_m1;
    for (int i = t; i < n; i += 256) {
        unsigned key = keys[i];
        int bin = (int)(key >> 21);
        if (bin > binb) {
            d_w[start + i] = key_score(key) * invk;
        } else if (bin < binb) {
            d_w[start + i] = 0.0f;
        } else {
            int c = atomicAdd(&s_ncand, 1);
            cand_idx[c] = i;
            cand_key[c] = key;
        }
    }
    __syncthreads();

    int r = k - m1;
    int nc = s_ncand;
    for (int c = t; c < nc; c += 256) {
        unsigned ki = cand_key[c];
        int ii = cand_idx[c];
        int cnt = 0;
        for (int j = 0; j < nc; ++j) {
            unsigned kj = cand_key[j];
            cnt += (kj > ki) || (kj == ki && cand_idx[j] < ii);
        }
        d_w[start + ii] = (cnt < r) ? key_score(ki) * invk : 0.0f;
    }
}

// ---------------------------------------------------------------------------
// K3: pooling. Compact kept rows to smem first (order-free), then a
// branch-free dense float4 stream over the kept list.
// ---------------------------------------------------------------------------
__global__ void k_pool(const float* __restrict__ x,
                       float* __restrict__ out) {
    __shared__ float sw[PCHUNKMX];
    __shared__ int   sidx[PCHUNKMX];
    __shared__ int   s_nk;
    __shared__ float ps[16][64];

    int g  = blockIdx.x >> 2;
    int sp = blockIdx.x & 3;
    int start = d_starts[g];
    int n = d_starts[g + 1] - start;
    int chunk = (n + PSPLIT - 1) / PSPLIT;
    int r0 = start + sp * chunk;
    int r1 = r0 + chunk; { int lim = start + n; if (r1 > lim) r1 = lim; }
    int len = r1 - r0;
    int t = threadIdx.x;
    int q  = t & 15;        // col quad
    int rg = t >> 4;        // row group (16)

    const float4* xv = (const float4*)x;
    float4 acc = make_float4(0.f, 0.f, 0.f, 0.f);

    if (t == 0) s_nk = 0;
    __syncthreads();

    if (len <= PCHUNKMX) {
        // compact kept rows (order irrelevant for a sum)
        for (int i = t; i < len; i += 256) {
            float w = d_w[r0 + i];
            if (w != 0.0f) {
                int c = atomicAdd(&s_nk, 1);
                sw[c] = w;
                sidx[c] = r0 + i;
            }
        }
        __syncthreads();
        int nk = s_nk;
#pragma unroll 4
        for (int j = rg; j < nk; j += 16) {
            float w = sw[j];
            int row = sidx[j];
            float4 v = xv[(size_t)row * 16 + q];
            acc.x += w * v.x; acc.y += w * v.y;
            acc.z += w * v.z; acc.w += w * v.w;
        }
    } else {
        for (int row = r0 + rg; row < r1; row += 16) {
            float w = d_w[row];
            if (w != 0.0f) {
                float4 v = xv[(size_t)row * 16 + q];
                acc.x += w * v.x; acc.y += w * v.y;
                acc.z += w * v.z; acc.w += w * v.w;
            }
        }
        __syncthreads();
    }

    ps[rg][q * 4 + 0] = acc.x;
    ps[rg][q * 4 + 1] = acc.y;
    ps[rg][q * 4 + 2] = acc.z;
    ps[rg][q * 4 + 3] = acc.w;
    __syncthreads();
    if (t < 64) {
        float v = 0.0f;
#pragma unroll
        for (int j = 0; j < 16; ++j) v += ps[j][t];
        if (v != 0.0f) atomicAdd(&out[g * 64 + t], v);
    }
}

// ---------------------------------------------------------------------------
extern "C" void kernel_launch(void* const* d_in, const int* in_sizes, int n_in,
                              void* d_out, int out_size) {
    const float* x      = (const float*)d_in[0];
    const int*   ei     = (const int*)d_in[1];
    const int*   batch  = (const int*)d_in[2];
    const float* w_rel  = (const float*)d_in[3];
    const float* b_rel  = (const float*)d_in[4];
    const float* w_root = (const float*)d_in[5];
    float*       out    = (float*)d_out;

    int N = in_sizes[2];
    int E = in_sizes[1] / 2;

    {
        long long threads = (long long)N * 8;
        int blocks = (int)((threads + 255) / 256);
        k_node_dots<<<blocks, 256>>>(x, w_rel, w_root, out, N);
    }
    {
        int E8 = E >> 3;
        if (E8 > 0)
            k_edge_scatter8<<<(E8 + 255) / 256, 256>>>(ei, E);
        int rem = E - (E8 << 3);
        if (rem > 0)
            k_edge_scatter_tail<<<(rem + 255) / 256, 256>>>(ei, E8 << 3, E);
    }
    k_rank<<<NGRAPH, 256>>>(batch, b_rel, N);
    k_pool<<<NGRAPH * PSPLIT, 256>>>(x, out);
}

// round 8
// speedup vs baseline: 1.5610x; 1.0035x over previous
#include <cuda_runtime.h>
#include <math.h>

#define MAX_N    131072
#define NGRAPH   256
#define MAXSEG   1024
#define PSPLIT   4
#define NBINS    2048
#define CHUNKB   8       // bins per thread (2048/256)

// Scratch (static __device__ arrays — no allocation allowed)
__device__ float d_p[MAX_N];        // x[i] . w_rel
__device__ float d_r[MAX_N];        // x[i] . w_root
__device__ float d_s[MAX_N];        // segment-summed p over edges
__device__ float d_score[MAX_N];    // fallback scratch only
__device__ float d_kw[MAX_N];       // compacted kept weights (score/k)
__device__ int   d_kidx[MAX_N];     // compacted kept global row indices
__device__ int   d_kcnt[NGRAPH];    // kept count per graph
__device__ int   d_starts[NGRAPH + 1];

__device__ __forceinline__ unsigned score_key(float s) {
    unsigned u = __float_as_uint(s);
    return (u & 0x80000000u) ? ~u : (u | 0x80000000u);   // monotone
}
__device__ __forceinline__ float key_score(unsigned k) {
    return (k & 0x80000000u) ? __uint_as_float(k & 0x7fffffffu)
                             : __uint_as_float(~k);
}
__device__ __forceinline__ int lower_bound_i(const int* a, int n, int v) {
    int lo = 0, hi = n;
    while (lo < hi) {
        int mid = (lo + hi) >> 1;
        if (a[mid] < v) lo = mid + 1; else hi = mid;
    }
    return lo;
}
__device__ __forceinline__ float dot4(float4 a, float4 b) {
    return a.x * b.x + a.y * b.y + a.z * b.z + a.w * b.w;
}

// ---------------------------------------------------------------------------
// K0: per-node dots p = x.w_rel, r = x.w_root ; zero s ; zero out.
// ---------------------------------------------------------------------------
__global__ void k_node_dots(const float* __restrict__ x,
                            const float* __restrict__ w_rel,
                            const float* __restrict__ w_root,
                            float* __restrict__ out,
                            int N) {
    int gid = blockIdx.x * blockDim.x + threadIdx.x;
    if (gid < NGRAPH * 64) out[gid] = 0.0f;
    int node = gid >> 3;
    if (node >= N) return;
    int sub = gid & 7;
    const float4* xr = (const float4*)(x + (size_t)node * 64);
    float4 v0 = xr[sub];
    float4 v1 = xr[sub + 8];
    const float4* wrv = (const float4*)w_rel;
    const float4* wtv = (const float4*)w_root;
    float a = dot4(v0, wrv[sub]) + dot4(v1, wrv[sub + 8]);
    float b = dot4(v0, wtv[sub]) + dot4(v1, wtv[sub + 8]);
#pragma unroll
    for (int o = 4; o; o >>= 1) {
        a += __shfl_xor_sync(0xffffffffu, a, o);
        b += __shfl_xor_sync(0xffffffffu, b, o);
    }
    if (sub == 0) {
        d_p[node] = a;
        d_r[node] = b;
        d_s[node] = 0.0f;
    }
}

// ---------------------------------------------------------------------------
// K1: edge scatter  s[dst] += p[src].  8 edges/thread for MLP.
// ---------------------------------------------------------------------------
__global__ void k_edge_scatter8(const int* __restrict__ ei, int E) {
    int t = blockIdx.x * blockDim.x + threadIdx.x;
    int E8 = E >> 3;
    if (t >= E8) return;
    const int4* sv = (const int4*)ei;
    const int4* dv = (const int4*)(ei + E);
    int4 sa = sv[2 * t], sb = sv[2 * t + 1];
    int4 da = dv[2 * t], db = dv[2 * t + 1];
    float p0 = d_p[sa.x], p1 = d_p[sa.y], p2 = d_p[sa.z], p3 = d_p[sa.w];
    float p4 = d_p[sb.x], p5 = d_p[sb.y], p6 = d_p[sb.z], p7 = d_p[sb.w];
    atomicAdd(&d_s[da.x], p0);
    atomicAdd(&d_s[da.y], p1);
    atomicAdd(&d_s[da.z], p2);
    atomicAdd(&d_s[da.w], p3);
    atomicAdd(&d_s[db.x], p4);
    atomicAdd(&d_s[db.y], p5);
    atomicAdd(&d_s[db.z], p6);
    atomicAdd(&d_s[db.w], p7);
}
__global__ void k_edge_scatter_tail(const int* __restrict__ ei, int base, int E) {
    int t = base + blockIdx.x * blockDim.x + threadIdx.x;
    if (t < E) atomicAdd(&d_s[ei[E + t]], d_p[ei[t]]);
}

// ---------------------------------------------------------------------------
// K2: per-graph fused score+select (histogram top-k, exact lexsort ties).
// Emits a COMPACTED kept-list (d_kw, d_kidx, d_kcnt) -- order irrelevant.
// ---------------------------------------------------------------------------
__global__ void k_rank(const int* __restrict__ batch,
                       const float* __restrict__ b_rel,
                       int N) {
    __shared__ unsigned keys[MAXSEG];
    __shared__ unsigned hist[NBINS];
    __shared__ unsigned chsum[256];
    __shared__ unsigned suf[256];
    __shared__ int s_se[2];
    __shared__ int s_bin, s_m1, s_ncand, s_nk;
    __shared__ int cand_idx[MAXSEG];
    __shared__ unsigned cand_key[MAXSEG];

    int g = blockIdx.x;
    int t = threadIdx.x;

    if (t < 2) s_se[t] = lower_bound_i(batch, N, g + t);
    if (t == 0) { s_bin = -1; s_m1 = 0; s_ncand = 0; s_nk = 0; d_kcnt[g] = 0; }
#pragma unroll
    for (int b = 0; b < CHUNKB; ++b) hist[t * CHUNKB + b] = 0;
    __syncthreads();

    int start = s_se[0];
    int end   = s_se[1];
    int n = end - start;
    if (t == 0) d_starts[g] = start;
    if (t == 1 && g == NGRAPH - 1) d_starts[NGRAPH] = end;

    int k = (n + 1) >> 1;
    float invk = 1.0f / fmaxf((float)k, 1.0f);
    float bias = b_rel[0];

    if (n > MAXSEG) {
        // improbable fallback: O(n^2), compact via global atomic
        for (int i = t; i < n; i += 256)
            d_score[start + i] = tanhf(d_s[start + i] + bias + d_r[start + i]);
        __syncthreads();
        for (int i = t; i < n; i += 256) {
            float si = d_score[start + i];
            int cnt = 0;
            for (int j = 0; j < i; ++j)     cnt += (d_score[start + j] >= si);
            for (int j = i + 1; j < n; ++j) cnt += (d_score[start + j] >  si);
            if (cnt < k) {
                int c = atomicAdd(&d_kcnt[g], 1);
                d_kw[start + c] = si * invk;
                d_kidx[start + c] = start + i;
            }
        }
        return;
    }

    for (int i = t; i < n; i += 256) {
        float sc = tanhf(d_s[start + i] + bias + d_r[start + i]);
        unsigned key = score_key(sc);
        keys[i] = key;
        atomicAdd(&hist[key >> 21], 1u);
    }
    __syncthreads();

    unsigned cs = 0;
#pragma unroll
    for (int b = 0; b < CHUNKB; ++b) cs += hist[t * CHUNKB + b];
    chsum[t] = cs;
    __syncthreads();

    // single-warp suffix scan over 256 chunk sums
    if (t < 32) {
        unsigned v[8];
        unsigned tot = 0;
#pragma unroll
        for (int j = 7; j >= 0; --j) {
            tot += chsum[t * 8 + j];
            v[j] = tot;
        }
        unsigned run = tot;
#pragma unroll
        for (int off = 1; off < 32; off <<= 1) {
            unsigned q = __shfl_down_sync(0xffffffffu, run, off);
            if (t + off < 32) run += q;
        }
        unsigned tail = run - tot;
#pragma unroll
        for (int j = 0; j < 8; ++j) suf[t * 8 + j] = v[j] + tail;
    }
    __syncthreads();

    {
        unsigned above = suf[t] - chsum[t];
        if ((int)above < k && k <= (int)suf[t]) {
            int acc = (int)above;
            for (int b = CHUNKB - 1; b >= 0; --b) {
                int h = (int)hist[t * CHUNKB + b];
                if (acc < k && k <= acc + h) { s_bin = t * CHUNKB + b; s_m1 = acc; }
                acc += h;
            }
        }
    }
    __syncthreads();

    int binb = s_bin, m1 = s_m1;
    for (int i = t; i < n; i += 256) {
        unsigned key = keys[i];
        int bin = (int)(key >> 21);
        if (bin > binb) {
            int c = atomicAdd(&s_nk, 1);
            d_kw[start + c] = key_score(key) * invk;
            d_kidx[start + c] = start + i;
        } else if (bin == binb) {
            int c = atomicAdd(&s_ncand, 1);
            cand_idx[c] = i;
            cand_key[c] = key;
        }
    }
    __syncthreads();

    int r = k - m1;
    int nc = s_ncand;
    for (int c = t; c < nc; c += 256) {
        unsigned ki = cand_key[c];
        int ii = cand_idx[c];
        int cnt = 0;
        for (int j = 0; j < nc; ++j) {
            unsigned kj = cand_key[j];
            cnt += (kj > ki) || (kj == ki && cand_idx[j] < ii);
        }
        if (cnt < r) {
            int cc = atomicAdd(&s_nk, 1);
            d_kw[start + cc] = key_score(ki) * invk;
            d_kidx[start + cc] = start + ii;
        }
    }
    __syncthreads();
    if (t == 0) d_kcnt[g] = s_nk;
}

// ---------------------------------------------------------------------------
// K3: pooling over the dense compacted kept-list. Branch-free float4 stream.
// ---------------------------------------------------------------------------
__global__ void k_pool(const float* __restrict__ x,
                       float* __restrict__ out) {
    __shared__ float ps[16][64];

    int g  = blockIdx.x >> 2;
    int sp = blockIdx.x & 3;
    int base = d_starts[g];
    int nk = d_kcnt[g];
    int chunk = (nk + PSPLIT - 1) / PSPLIT;
    int j0 = sp * chunk;
    int j1 = j0 + chunk; if (j1 > nk) j1 = nk;
    int t = threadIdx.x;
    int q  = t & 15;        // col quad
    int rg = t >> 4;        // row group (16)

    const float4* xv = (const float4*)x;
    float4 acc = make_float4(0.f, 0.f, 0.f, 0.f);

#pragma unroll 4
    for (int j = j0 + rg; j < j1; j += 16) {
        float w  = d_kw[base + j];
        int row  = d_kidx[base + j];
        float4 v = xv[(size_t)row * 16 + q];
        acc.x += w * v.x; acc.y += w * v.y;
        acc.z += w * v.z; acc.w += w * v.w;
    }

    ps[rg][q * 4 + 0] = acc.x;
    ps[rg][q * 4 + 1] = acc.y;
    ps[rg][q * 4 + 2] = acc.z;
    ps[rg][q * 4 + 3] = acc.w;
    __syncthreads();
    if (t < 64) {
        float v = 0.0f;
#pragma unroll
        for (int j = 0; j < 16; ++j) v += ps[j][t];
        if (v != 0.0f) atomicAdd(&out[g * 64 + t], v);
    }
}

// ---------------------------------------------------------------------------
extern "C" void kernel_launch(void* const* d_in, const int* in_sizes, int n_in,
                              void* d_out, int out_size) {
    const float* x      = (const float*)d_in[0];
    const int*   ei     = (const int*)d_in[1];
    const int*   batch  = (const int*)d_in[2];
    const float* w_rel  = (const float*)d_in[3];
    const float* b_rel  = (const float*)d_in[4];
    const float* w_root = (const float*)d_in[5];
    float*       out    = (float*)d_out;

    int N = in_sizes[2];
    int E = in_sizes[1] / 2;

    {
        long long threads = (long long)N * 8;
        int blocks = (int)((threads + 255) / 256);
        k_node_dots<<<blocks, 256>>>(x, w_rel, w_root, out, N);
    }
    {
        int E8 = E >> 3;
        if (E8 > 0)
            k_edge_scatter8<<<(E8 + 255) / 256, 256>>>(ei, E);
        int rem = E - (E8 << 3);
        if (rem > 0)
            k_edge_scatter_tail<<<(rem + 255) / 256, 256>>>(ei, E8 << 3, E);
    }
    k_rank<<<NGRAPH, 256>>>(batch, b_rel, N);
    k_pool<<<NGRAPH * PSPLIT, 256>>>(x, out);
}